// round 10
// baseline (speedup 1.0000x reference)
#include <cuda_runtime.h>
#include <cuda_fp16.h>
#include <cstdint>
#include <cstddef>

// Problem constants
#define B   4
#define S   2048
#define E   2048
#define H   16
#define DH  128
#define BS  (B*S)   // 8192

// fp16 scratch
__device__ __half g_Q [(size_t)B*H*S*DH];          // [bh][S][DH]
__device__ __half g_K [(size_t)B*H*S*DH];          // [bh][S][DH]
__device__ __half g_Vt[(size_t)B*H*S*DH];          // [bh][DH][S]  (transposed)
__device__ __half g_Xh[(size_t)BS*E];              // [BS][E]
__device__ __half g_Wtq[(size_t)H*DH*E];           // [H][DH][E]   (transposed)
__device__ __half g_Wtk[(size_t)H*DH*E];
__device__ __half g_Wtv[(size_t)H*DH*E];

// ---------------------------------------------------------------------------
// helpers
// ---------------------------------------------------------------------------
__device__ __forceinline__ unsigned smaddr(const void* p) {
    return (unsigned)__cvta_generic_to_shared(p);
}
__device__ __forceinline__ void cp16(void* smem_dst, const void* gmem_src) {
    unsigned d = smaddr(smem_dst);
    asm volatile("cp.async.cg.shared.global [%0], [%1], 16;\n" :: "r"(d), "l"(gmem_src));
}
__device__ __forceinline__ void cp_commit() { asm volatile("cp.async.commit_group;\n"); }
__device__ __forceinline__ void cp_wait1()  { asm volatile("cp.async.wait_group 1;\n"); }
__device__ __forceinline__ void cp_wait0()  { asm volatile("cp.async.wait_group 0;\n"); }

__device__ __forceinline__ void ldsm4(unsigned& r0, unsigned& r1, unsigned& r2, unsigned& r3,
                                      unsigned addr) {
    asm volatile("ldmatrix.sync.aligned.m8n8.x4.shared.b16 {%0,%1,%2,%3}, [%4];"
        : "=r"(r0), "=r"(r1), "=r"(r2), "=r"(r3) : "r"(addr));
}
__device__ __forceinline__ void mma_f16(float c[4], const unsigned a[4], const unsigned b[2]) {
    asm volatile("mma.sync.aligned.m16n8k16.row.col.f32.f16.f16.f32 "
        "{%0,%1,%2,%3}, {%4,%5,%6,%7}, {%8,%9}, {%0,%1,%2,%3};"
        : "+f"(c[0]), "+f"(c[1]), "+f"(c[2]), "+f"(c[3])
        : "r"(a[0]), "r"(a[1]), "r"(a[2]), "r"(a[3]), "r"(b[0]), "r"(b[1]));
}
__device__ __forceinline__ unsigned pack2(float lo, float hi) {
    __half2 h = __floats2half2_rn(lo, hi);
    return *reinterpret_cast<unsigned*>(&h);
}
// 2^lo, 2^hi as packed fp16 (lo in low half)
__device__ __forceinline__ unsigned exp2h2(float lo, float hi) {
    unsigned r;
    asm("{\n\t.reg .b32 t;\n\t"
        "cvt.rn.f16x2.f32 t, %2, %1;\n\t"    // first src -> high half
        "ex2.approx.f16x2 %0, t;\n\t}"
        : "=r"(r) : "f"(lo), "f"(hi));
    return r;
}

// ---------------------------------------------------------------------------
// Kernel 0a: X f32 -> f16 elementwise
// ---------------------------------------------------------------------------
__global__ void convX(const float* __restrict__ src, __half* __restrict__ dst, int n4)
{
    const float4* s = (const float4*)src;
    uint2*        d = (uint2*)dst;
    for (int i = blockIdx.x * blockDim.x + threadIdx.x; i < n4; i += gridDim.x * blockDim.x) {
        float4 v = s[i];
        uint2 o;
        o.x = pack2(v.x, v.y);
        o.y = pack2(v.z, v.w);
        d[i] = o;
    }
}

// ---------------------------------------------------------------------------
// Kernel 0b: W [H][E][DH] f32 -> Wt [H][DH][E] f16 (tiled transpose)
// ---------------------------------------------------------------------------
__global__ void convWT(const float* __restrict__ Wq, const float* __restrict__ Wk,
                       const float* __restrict__ Wv,
                       __half* __restrict__ Tq, __half* __restrict__ Tk,
                       __half* __restrict__ Tv)
{
    __shared__ float tile[32][33];
    const int zz = blockIdx.z;
    const int z  = zz >> 4;
    const int h  = zz & 15;
    const float* Wsrc = (z == 0 ? Wq : (z == 1 ? Wk : Wv)) + (size_t)h * E * DH;
    __half*      Tdst = (z == 0 ? Tq : (z == 1 ? Tk : Tv)) + (size_t)h * DH * E;

    const int d0 = blockIdx.x * 32;
    const int e0 = blockIdx.y * 32;
    const int tx = threadIdx.x, ty = threadIdx.y;

    #pragma unroll
    for (int j = 0; j < 4; j++) {
        int e = e0 + ty + j * 8;
        tile[ty + j * 8][tx] = Wsrc[(size_t)e * DH + d0 + tx];
    }
    __syncthreads();
    #pragma unroll
    for (int j = 0; j < 4; j++) {
        int d = d0 + ty + j * 8;
        Tdst[(size_t)d * E + e0 + tx] = __float2half(tile[tx][ty + j * 8]);
    }
}

// ---------------------------------------------------------------------------
// Kernel 1: QKV GEMM, mma.m16n8k16 f16/f32 + ldmatrix, 3-stage cp.async ring.
//   Block 128(M) x 256(N = 2 heads) x 64(K halves), 512 threads,
//   16 warps = 4(m) x 4(n), warp tile 32x64. 1 CTA/SM (16 warps = 4/SMSP).
//   Halves X L2 traffic vs the 1-head tile (24 CTAs re-read X, not 48).
// ---------------------------------------------------------------------------
#define QKC 64
#define XLD2 72
#define WLD2 72
#define XST2 (128*XLD2)     // 9216 halves
#define WST2 (256*WLD2)     // 18432 halves
#define QKV_SMEM_BYTES ((3*(XST2+WST2))*2)   // 165,888 B

__global__ __launch_bounds__(512, 1) void qkv_kernel()
{
    extern __shared__ __half smh[];
    __half* Xs[3] = { smh, smh + XST2, smh + 2*XST2 };
    __half* Ws[3] = { smh + 3*XST2, smh + 3*XST2 + WST2, smh + 3*XST2 + 2*WST2 };

    const int hp   = blockIdx.x;   // head pair 0..7
    const int mblk = blockIdx.y;
    const int z    = blockIdx.z;
    const int h0   = hp * 2;

    // two heads' Wt rows are contiguous: (h0*DH + row)*E, row in [0,256)
    const __half* Wb = (z == 0 ? g_Wtq : (z == 1 ? g_Wtk : g_Wtv)) + (size_t)h0 * DH * E;

    const int tx   = threadIdx.x;
    const int lane = tx & 31;
    const int wid  = tx >> 5;
    const int warp_m = wid >> 2;   // 0..3 : 32 rows
    const int warp_n = wid & 3;    // 0..3 : 64 cols of 256
    const int g  = lane >> 2;
    const int t4 = lane & 3;
    const int m0 = mblk * 128;

    const int a_row  = (lane & 7) + ((lane >> 3) & 1) * 8;
    const int a_col  = (lane >> 4) * 8;
    const int b_row  = (lane & 7) + (lane >> 4) * 8;
    const int b_col  = ((lane >> 3) & 1) * 8;

    float c[2][8][4];
    #pragma unroll
    for (int mi = 0; mi < 2; mi++)
        #pragma unroll
        for (int ni = 0; ni < 8; ni++)
            #pragma unroll
            for (int e = 0; e < 4; e++) c[mi][ni][e] = 0.0f;

    const __half* Xg = g_Xh + (size_t)m0 * E;

    auto issue = [&](int kt, int st) {
        #pragma unroll
        for (int i = 0; i < 2; i++) {
            int idx  = tx + 512 * i;          // 0..1023
            int row  = idx >> 3;              // 0..127
            int col8 = (idx & 7) * 8;
            cp16(Xs[st] + row * XLD2 + col8, Xg + (size_t)row * E + kt * QKC + col8);
        }
        #pragma unroll
        for (int i = 0; i < 4; i++) {
            int idx  = tx + 512 * i;          // 0..2047
            int row  = idx >> 3;              // 0..255
            int col8 = (idx & 7) * 8;
            cp16(Ws[st] + row * WLD2 + col8, Wb + (size_t)row * E + kt * QKC + col8);
        }
        cp_commit();
    };

    const int NK = E / QKC;   // 32
    issue(0, 0);
    issue(1, 1);

    for (int kt = 0; kt < NK; kt++) {
        if (kt + 1 < NK) cp_wait1(); else cp_wait0();
        __syncthreads();
        if (kt + 2 < NK) issue(kt + 2, (kt + 2) % 3);

        const __half* Xt = Xs[kt % 3];
        const __half* Wt = Ws[kt % 3];
        #pragma unroll
        for (int ks = 0; ks < 4; ks++) {
            unsigned a[2][4];
            #pragma unroll
            for (int mi = 0; mi < 2; mi++)
                ldsm4(a[mi][0], a[mi][1], a[mi][2], a[mi][3],
                      smaddr(Xt + (warp_m * 32 + mi * 16 + a_row) * XLD2 + ks * 16 + a_col));
            #pragma unroll
            for (int pr = 0; pr < 4; pr++) {
                unsigned b4[4];
                ldsm4(b4[0], b4[1], b4[2], b4[3],
                      smaddr(Wt + (warp_n * 64 + pr * 16 + b_row) * WLD2 + ks * 16 + b_col));
                unsigned b01[2] = { b4[0], b4[1] };
                unsigned b23[2] = { b4[2], b4[3] };
                mma_f16(c[0][2 * pr],     a[0], b01);
                mma_f16(c[0][2 * pr + 1], a[0], b23);
                mma_f16(c[1][2 * pr],     a[1], b01);
                mma_f16(c[1][2 * pr + 1], a[1], b23);
            }
        }
    }

    // epilogue: column -> (head, d) split
    const int bbatch = m0 / S;
    const int s0     = m0 % S;
    const int bh0    = bbatch * H + h0;
    if (z < 2) {
        __half* base = (z == 0 ? g_Q : g_K);
        #pragma unroll
        for (int mi = 0; mi < 2; mi++) {
            const int r0 = warp_m * 32 + mi * 16 + g;
            #pragma unroll
            for (int ni = 0; ni < 8; ni++) {
                const int ncol = warp_n * 64 + ni * 8 + 2 * t4;
                const int head = ncol >> 7;
                const int dcol = ncol & 127;
                __half* Ob = base + ((size_t)(bh0 + head) * S + s0 + r0) * DH + dcol;
                *reinterpret_cast<unsigned*>(Ob)            = pack2(c[mi][ni][0], c[mi][ni][1]);
                *reinterpret_cast<unsigned*>(Ob + 8 * DH)   = pack2(c[mi][ni][2], c[mi][ni][3]);
            }
        }
    } else {
        #pragma unroll
        for (int mi = 0; mi < 2; mi++) {
            const int r0 = warp_m * 32 + mi * 16 + g;
            #pragma unroll
            for (int ni = 0; ni < 8; ni++) {
                const int ncol = warp_n * 64 + ni * 8 + 2 * t4;
                const int head = ncol >> 7;
                const int dcol = ncol & 127;
                __half* Ob = g_Vt + (size_t)(bh0 + head) * DH * S + s0;
                Ob[(size_t)dcol * S + r0]           = __float2half(c[mi][ni][0]);
                Ob[(size_t)(dcol + 1) * S + r0]     = __float2half(c[mi][ni][1]);
                Ob[(size_t)dcol * S + r0 + 8]       = __float2half(c[mi][ni][2]);
                Ob[(size_t)(dcol + 1) * S + r0 + 8] = __float2half(c[mi][ni][3]);
            }
        }
    }
}

// ---------------------------------------------------------------------------
// Kernel 2: causal flash attention, FA2 warp layout (unchanged from R9).
//   CTA = 128 q-rows of one (b,h); 8 warps x 16 full rows. Q frags hoisted.
//   3-stage K/V ring, ONE __syncthreads per KV tile. ex2.approx.f16x2
//   softmax; row-sum l via ones-B mma.
// ---------------------------------------------------------------------------
#define QLD 136    // halves; 272 B == 16 mod 128 -> conflict-free ldmatrix
#define VLD 72     // halves; 144 B == 16 mod 128
#define KSTG (64*QLD)
#define VSTG (128*VLD)
#define ATTN_SMEM_BYTES ((128*QLD + 3*KSTG + 3*VSTG) * 2)   // 142,336 B

#define SCALE_LOG2E 0.12751744654974748f   // log2(e)/sqrt(128)

__global__ __launch_bounds__(256, 1) void attn_kernel(float* __restrict__ out)
{
    extern __shared__ __half smh[];
    __half* Qs  = smh;                    // 128 x QLD
    __half* Ks  = Qs + 128*QLD;           // 3 x 64 x QLD
    __half* VTs = Ks + 3*KSTG;            // 3 x 128 x VLD  (V transposed [d][s])

    const int qb = blockIdx.x;
    const int bh = blockIdx.y;
    const int b  = bh >> 4;
    const int h  = bh & 15;
    const int q0 = qb * 128;
    const int tid  = threadIdx.x;
    const int lane = tid & 31;
    const int wid  = tid >> 5;
    const int g  = lane >> 2;
    const int t4 = lane & 3;
    const int rlo = wid * 16 + g;
    const int rhi = rlo + 8;

    const int a_row = wid * 16 + (lane & 7) + ((lane >> 3) & 1) * 8;
    const int a_col = (lane >> 4) * 8;
    const int b_row = (lane & 7) + (lane >> 4) * 8;
    const int b_col = ((lane >> 3) & 1) * 8;

    const __half* Kg0 = g_K  + (size_t)bh * S * DH;
    const __half* Vg0 = g_Vt + (size_t)bh * DH * S;

    auto issue_kv = [&](int kb, int st) {
        const __half* Kg = Kg0 + (size_t)kb * 64 * DH;
        const __half* Vg = Vg0 + (size_t)kb * 64;
        __half* Kd = Ks  + st * KSTG;
        __half* Vd = VTs + st * VSTG;
        const int krow = tid >> 2, k1 = tid & 3;
        #pragma unroll
        for (int i = 0; i < 2; i++) {
            const int col = (k1 + 4 * i) * 16;
            cp16(Kd + krow * QLD + col,     Kg + (size_t)krow * DH + col);
            cp16(Kd + krow * QLD + col + 8, Kg + (size_t)krow * DH + col + 8);
        }
        const int vrow = tid >> 1, v1 = tid & 1;
        #pragma unroll
        for (int i = 0; i < 4; i++) {
            const int vc = (v1 + 2 * i) * 8;
            cp16(Vd + vrow * VLD + vc, Vg + (size_t)vrow * S + vc);
        }
        cp_commit();
    };

    // group 0: Q + K0/V0 ; group 1: K1/V1
    {
        const __half* Qg = g_Q + ((size_t)bh * S + q0) * DH;
        const int qrow = tid >> 1, q1 = tid & 1;
        #pragma unroll
        for (int i = 0; i < 4; i++) {
            const int col = (q1 + 2 * i) * 8;
            cp16(Qs + qrow * QLD + col,      Qg + (size_t)qrow * DH + col);
            cp16(Qs + qrow * QLD + col + 64, Qg + (size_t)qrow * DH + col + 64);
        }
        issue_kv(0, 0);   // commits Q + KV0 together
    }
    issue_kv(1, 1);

    float oacc[16][4];
    #pragma unroll
    for (int i = 0; i < 16; i++)
        #pragma unroll
        for (int j = 0; j < 4; j++) oacc[i][j] = 0.0f;
    float lacc[4] = {0.f, 0.f, 0.f, 0.f};

    unsigned qa[8][4];
    float m0r = -3.0e38f, m1r = -3.0e38f;
    const unsigned ONES2 = 0x3C003C00u;   // half2(1,1)
    const unsigned onesb[2] = { ONES2, ONES2 };

    const int NT = 2 * qb + 2;
    for (int kb = 0; kb < NT; kb++) {
        if (kb + 1 < NT) cp_wait1(); else cp_wait0();
        __syncthreads();
        if (kb + 2 < NT) issue_kv(kb + 2, (kb + 2) % 3);

        if (kb == 0) {   // hoist Q fragments once
            #pragma unroll
            for (int ks = 0; ks < 8; ks++)
                ldsm4(qa[ks][0], qa[ks][1], qa[ks][2], qa[ks][3],
                      smaddr(Qs + a_row * QLD + ks * 16 + a_col));
        }

        const __half* Kb_ = Ks  + (kb % 3) * KSTG;
        const __half* Vb_ = VTs + (kb % 3) * VSTG;
        const int k0 = kb * 64;

        // ---- scores ----
        float c[8][4];
        #pragma unroll
        for (int nf = 0; nf < 8; nf++)
            #pragma unroll
            for (int e = 0; e < 4; e++) c[nf][e] = 0.0f;

        #pragma unroll
        for (int ks = 0; ks < 8; ks++) {
            #pragma unroll
            for (int pr = 0; pr < 4; pr++) {
                unsigned b4[4];
                ldsm4(b4[0], b4[1], b4[2], b4[3],
                      smaddr(Kb_ + (pr * 16 + b_row) * QLD + ks * 16 + b_col));
                unsigned b01[2] = { b4[0], b4[1] };
                unsigned b23[2] = { b4[2], b4[3] };
                mma_f16(c[2 * pr],     qa[ks], b01);
                mma_f16(c[2 * pr + 1], qa[ks], b23);
            }
        }

        // scale (log2 domain) + causal mask
        #pragma unroll
        for (int nf = 0; nf < 8; nf++)
            #pragma unroll
            for (int e = 0; e < 4; e++) c[nf][e] *= SCALE_LOG2E;
        if (kb >= 2 * qb) {
            #pragma unroll
            for (int nf = 0; nf < 8; nf++) {
                const int key = k0 + nf * 8 + 2 * t4;
                if (key     > q0 + rlo) c[nf][0] = -1.0e30f;
                if (key + 1 > q0 + rlo) c[nf][1] = -1.0e30f;
                if (key     > q0 + rhi) c[nf][2] = -1.0e30f;
                if (key + 1 > q0 + rhi) c[nf][3] = -1.0e30f;
            }
        }

        // ---- warp-private online softmax (base-2) ----
        float mx0 = -3.0e38f, mx1 = -3.0e38f;
        #pragma unroll
        for (int nf = 0; nf < 8; nf++) {
            mx0 = fmaxf(mx0, fmaxf(c[nf][0], c[nf][1]));
            mx1 = fmaxf(mx1, fmaxf(c[nf][2], c[nf][3]));
        }
        mx0 = fmaxf(mx0, __shfl_xor_sync(0xffffffffu, mx0, 1));
        mx0 = fmaxf(mx0, __shfl_xor_sync(0xffffffffu, mx0, 2));
        mx1 = fmaxf(mx1, __shfl_xor_sync(0xffffffffu, mx1, 1));
        mx1 = fmaxf(mx1, __shfl_xor_sync(0xffffffffu, mx1, 2));
        const float mn0 = fmaxf(m0r, mx0);
        const float mn1 = fmaxf(m1r, mx1);
        const float cr0 = exp2f(m0r - mn0);
        const float cr1 = exp2f(m1r - mn1);
        m0r = mn0;
        m1r = mn1;

        // probabilities straight to fp16 a-fragments (2^x, packed)
        unsigned pa[4][4];
        #pragma unroll
        for (int ks = 0; ks < 4; ks++) {
            pa[ks][0] = exp2h2(c[2 * ks][0] - mn0,     c[2 * ks][1] - mn0);
            pa[ks][1] = exp2h2(c[2 * ks][2] - mn1,     c[2 * ks][3] - mn1);
            pa[ks][2] = exp2h2(c[2 * ks + 1][0] - mn0, c[2 * ks + 1][1] - mn0);
            pa[ks][3] = exp2h2(c[2 * ks + 1][2] - mn1, c[2 * ks + 1][3] - mn1);
        }

        // rescale O and l accumulators
        #pragma unroll
        for (int nf = 0; nf < 16; nf++) {
            oacc[nf][0] *= cr0; oacc[nf][1] *= cr0;
            oacc[nf][2] *= cr1; oacc[nf][3] *= cr1;
        }
        lacc[0] *= cr0; lacc[1] *= cr0; lacc[2] *= cr1; lacc[3] *= cr1;

        // ---- PV + row-sum mma ----
        #pragma unroll
        for (int ks = 0; ks < 4; ks++) {
            #pragma unroll
            for (int pr = 0; pr < 8; pr++) {
                unsigned b4[4];
                ldsm4(b4[0], b4[1], b4[2], b4[3],
                      smaddr(Vb_ + (pr * 16 + b_row) * VLD + ks * 16 + b_col));
                unsigned b01[2] = { b4[0], b4[1] };
                unsigned b23[2] = { b4[2], b4[3] };
                mma_f16(oacc[2 * pr],     pa[ks], b01);
                mma_f16(oacc[2 * pr + 1], pa[ks], b23);
            }
            mma_f16(lacc, pa[ks], onesb);   // l += P . 1
        }
    }

    // epilogue: normalize, round(x,4), write [B,S,H*DH]
    const float li0 = 1.0f / lacc[0];
    const float li1 = 1.0f / lacc[2];
    float* og0 = out + ((size_t)(b * S + q0 + rlo)) * (H * DH) + h * DH;
    float* og1 = out + ((size_t)(b * S + q0 + rhi)) * (H * DH) + h * DH;
    #pragma unroll
    for (int nf = 0; nf < 16; nf++) {
        const int col = nf * 8 + 2 * t4;
        float2 v0, v1;
        v0.x = rintf(oacc[nf][0] * li0 * 1.0e4f) * 1.0e-4f;
        v0.y = rintf(oacc[nf][1] * li0 * 1.0e4f) * 1.0e-4f;
        v1.x = rintf(oacc[nf][2] * li1 * 1.0e4f) * 1.0e-4f;
        v1.y = rintf(oacc[nf][3] * li1 * 1.0e4f) * 1.0e-4f;
        *reinterpret_cast<float2*>(og0 + col) = v0;
        *reinterpret_cast<float2*>(og1 + col) = v1;
    }
}

// ---------------------------------------------------------------------------
extern "C" void kernel_launch(void* const* d_in, const int* in_sizes, int n_in,
                              void* d_out, int out_size)
{
    const float* X  = (const float*)d_in[0];
    const float* Wq = (const float*)d_in[1];
    const float* Wk = (const float*)d_in[2];
    const float* Wv = (const float*)d_in[3];
    float* out = (float*)d_out;

    cudaFuncSetAttribute(qkv_kernel,  cudaFuncAttributeMaxDynamicSharedMemorySize, QKV_SMEM_BYTES);
    cudaFuncSetAttribute(attn_kernel, cudaFuncAttributeMaxDynamicSharedMemorySize, ATTN_SMEM_BYTES);

    static __half *pXh = nullptr, *pWq = nullptr, *pWk = nullptr, *pWv = nullptr;
    if (!pXh) {
        cudaGetSymbolAddress((void**)&pXh, g_Xh);
        cudaGetSymbolAddress((void**)&pWq, g_Wtq);
        cudaGetSymbolAddress((void**)&pWk, g_Wtk);
        cudaGetSymbolAddress((void**)&pWv, g_Wtv);
    }

    convX<<<2048, 256>>>(X, pXh, (int)((size_t)BS * E / 4));
    dim3 gt(DH / 32, E / 32, 3 * H);
    convWT<<<gt, dim3(32, 8)>>>(Wq, Wk, Wv, pWq, pWk, pWv);

    dim3 g1(H / 2, BS / 128, 3);
    qkv_kernel<<<g1, 512, QKV_SMEM_BYTES>>>();

    dim3 g2(S / 128, B * H);
    attn_kernel<<<g2, 256, ATTN_SMEM_BYTES>>>(out);
}

// round 11
// speedup vs baseline: 1.1078x; 1.1078x over previous
#include <cuda_runtime.h>
#include <cuda_fp16.h>
#include <cstdint>
#include <cstddef>

// Problem constants
#define B   4
#define S   2048
#define E   2048
#define H   16
#define DH  128
#define BS  (B*S)   // 8192

// fp16 scratch
__device__ __half g_Q [(size_t)B*H*S*DH];          // [bh][S][DH]
__device__ __half g_K [(size_t)B*H*S*DH];          // [bh][S][DH]
__device__ __half g_V [(size_t)B*H*S*DH];          // [bh][S][DH] (natural)
__device__ __half g_Xh[(size_t)BS*E];              // [BS][E]
__device__ __half g_Wtq[(size_t)H*DH*E];           // [H][DH][E]   (transposed)
__device__ __half g_Wtk[(size_t)H*DH*E];
__device__ __half g_Wtv[(size_t)H*DH*E];

// ---------------------------------------------------------------------------
// helpers
// ---------------------------------------------------------------------------
__device__ __forceinline__ unsigned smaddr(const void* p) {
    return (unsigned)__cvta_generic_to_shared(p);
}
__device__ __forceinline__ void cp16(void* smem_dst, const void* gmem_src) {
    unsigned d = smaddr(smem_dst);
    asm volatile("cp.async.cg.shared.global [%0], [%1], 16;\n" :: "r"(d), "l"(gmem_src));
}
__device__ __forceinline__ void cp_commit() { asm volatile("cp.async.commit_group;\n"); }
__device__ __forceinline__ void cp_wait1()  { asm volatile("cp.async.wait_group 1;\n"); }
__device__ __forceinline__ void cp_wait0()  { asm volatile("cp.async.wait_group 0;\n"); }

__device__ __forceinline__ void ldsm4(unsigned& r0, unsigned& r1, unsigned& r2, unsigned& r3,
                                      unsigned addr) {
    asm volatile("ldmatrix.sync.aligned.m8n8.x4.shared.b16 {%0,%1,%2,%3}, [%4];"
        : "=r"(r0), "=r"(r1), "=r"(r2), "=r"(r3) : "r"(addr));
}
__device__ __forceinline__ void ldsm4t(unsigned& r0, unsigned& r1, unsigned& r2, unsigned& r3,
                                       unsigned addr) {
    asm volatile("ldmatrix.sync.aligned.m8n8.x4.trans.shared.b16 {%0,%1,%2,%3}, [%4];"
        : "=r"(r0), "=r"(r1), "=r"(r2), "=r"(r3) : "r"(addr));
}
__device__ __forceinline__ void mma_f16(float c[4], const unsigned a[4], const unsigned b[2]) {
    asm volatile("mma.sync.aligned.m16n8k16.row.col.f32.f16.f16.f32 "
        "{%0,%1,%2,%3}, {%4,%5,%6,%7}, {%8,%9}, {%0,%1,%2,%3};"
        : "+f"(c[0]), "+f"(c[1]), "+f"(c[2]), "+f"(c[3])
        : "r"(a[0]), "r"(a[1]), "r"(a[2]), "r"(a[3]), "r"(b[0]), "r"(b[1]));
}
__device__ __forceinline__ unsigned pack2(float lo, float hi) {
    __half2 h = __floats2half2_rn(lo, hi);
    return *reinterpret_cast<unsigned*>(&h);
}
// 2^lo, 2^hi as packed fp16 (lo in low half)
__device__ __forceinline__ unsigned exp2h2(float lo, float hi) {
    unsigned r;
    asm("{\n\t.reg .b32 t;\n\t"
        "cvt.rn.f16x2.f32 t, %2, %1;\n\t"    // first src -> high half
        "ex2.approx.f16x2 %0, t;\n\t}"
        : "=r"(r) : "f"(lo), "f"(hi));
    return r;
}

// ---------------------------------------------------------------------------
// Kernel 0a: X f32 -> f16 elementwise
// ---------------------------------------------------------------------------
__global__ void convX(const float* __restrict__ src, __half* __restrict__ dst, int n4)
{
    const float4* s = (const float4*)src;
    uint2*        d = (uint2*)dst;
    for (int i = blockIdx.x * blockDim.x + threadIdx.x; i < n4; i += gridDim.x * blockDim.x) {
        float4 v = s[i];
        uint2 o;
        o.x = pack2(v.x, v.y);
        o.y = pack2(v.z, v.w);
        d[i] = o;
    }
}

// ---------------------------------------------------------------------------
// Kernel 0b: W [H][E][DH] f32 -> Wt [H][DH][E] f16 (tiled transpose)
// ---------------------------------------------------------------------------
__global__ void convWT(const float* __restrict__ Wq, const float* __restrict__ Wk,
                       const float* __restrict__ Wv,
                       __half* __restrict__ Tq, __half* __restrict__ Tk,
                       __half* __restrict__ Tv)
{
    __shared__ float tile[32][33];
    const int zz = blockIdx.z;
    const int z  = zz >> 4;
    const int h  = zz & 15;
    const float* Wsrc = (z == 0 ? Wq : (z == 1 ? Wk : Wv)) + (size_t)h * E * DH;
    __half*      Tdst = (z == 0 ? Tq : (z == 1 ? Tk : Tv)) + (size_t)h * DH * E;

    const int d0 = blockIdx.x * 32;
    const int e0 = blockIdx.y * 32;
    const int tx = threadIdx.x, ty = threadIdx.y;

    #pragma unroll
    for (int j = 0; j < 4; j++) {
        int e = e0 + ty + j * 8;
        tile[ty + j * 8][tx] = Wsrc[(size_t)e * DH + d0 + tx];
    }
    __syncthreads();
    #pragma unroll
    for (int j = 0; j < 4; j++) {
        int d = d0 + ty + j * 8;
        Tdst[(size_t)d * E + e0 + tx] = __float2half(tile[tx][ty + j * 8]);
    }
}

// ---------------------------------------------------------------------------
// Kernel 1: QKV GEMM, mma.m16n8k16 f16/f32 + ldmatrix, 3-stage cp.async ring
//   (R9 proven shape: 256 threads, 8 warps = 4m x 2n, 2 CTAs/SM).
//   Block 128(M) x 128(N = 1 head) x 64(K halves). ALL outputs (Q,K,V)
//   stored natural [bh][S][DH] with packed coalesced stores.
// ---------------------------------------------------------------------------
#define QKC 64
#define XLD2 72
#define WLD2 72
#define XST2 (128*XLD2)
#define WST2 (128*WLD2)
#define QKV_SMEM_BYTES ((3*(XST2+WST2))*2)   // 110,592 B

__global__ __launch_bounds__(256, 2) void qkv_kernel()
{
    extern __shared__ __half smh[];
    __half* Xs[3] = { smh, smh + XST2, smh + 2*XST2 };
    __half* Ws[3] = { smh + 3*XST2, smh + 3*XST2 + WST2, smh + 3*XST2 + 2*WST2 };

    const int h    = blockIdx.x;
    const int mblk = blockIdx.y;
    const int z    = blockIdx.z;

    const __half* Wb = (z == 0 ? g_Wtq : (z == 1 ? g_Wtk : g_Wtv)) + (size_t)h * DH * E;

    const int tx   = threadIdx.x;
    const int lane = tx & 31;
    const int wid  = tx >> 5;
    const int warp_m = wid >> 1;
    const int warp_n = wid & 1;
    const int g  = lane >> 2;
    const int t4 = lane & 3;
    const int m0 = mblk * 128;

    const int a_row  = (lane & 7) + ((lane >> 3) & 1) * 8;
    const int a_col  = (lane >> 4) * 8;
    const int b_row  = (lane & 7) + (lane >> 4) * 8;
    const int b_col  = ((lane >> 3) & 1) * 8;

    float c[2][8][4];
    #pragma unroll
    for (int mi = 0; mi < 2; mi++)
        #pragma unroll
        for (int ni = 0; ni < 8; ni++)
            #pragma unroll
            for (int e = 0; e < 4; e++) c[mi][ni][e] = 0.0f;

    const __half* Xg = g_Xh + (size_t)m0 * E;

    auto issue = [&](int kt, int st) {
        #pragma unroll
        for (int i = 0; i < 4; i++) {
            int idx  = tx + 256 * i;
            int row  = idx >> 3;
            int col8 = (idx & 7) * 8;
            cp16(Xs[st] + row * XLD2 + col8, Xg + (size_t)row * E + kt * QKC + col8);
            cp16(Ws[st] + row * WLD2 + col8, Wb + (size_t)row * E + kt * QKC + col8);
        }
        cp_commit();
    };

    const int NK = E / QKC;   // 32
    issue(0, 0);
    issue(1, 1);

    for (int kt = 0; kt < NK; kt++) {
        if (kt + 1 < NK) cp_wait1(); else cp_wait0();
        __syncthreads();
        if (kt + 2 < NK) issue(kt + 2, (kt + 2) % 3);

        const __half* Xt = Xs[kt % 3];
        const __half* Wt = Ws[kt % 3];
        #pragma unroll
        for (int ks = 0; ks < 4; ks++) {
            unsigned a[2][4];
            #pragma unroll
            for (int mi = 0; mi < 2; mi++)
                ldsm4(a[mi][0], a[mi][1], a[mi][2], a[mi][3],
                      smaddr(Xt + (warp_m * 32 + mi * 16 + a_row) * XLD2 + ks * 16 + a_col));
            #pragma unroll
            for (int pr = 0; pr < 4; pr++) {
                unsigned b4[4];
                ldsm4(b4[0], b4[1], b4[2], b4[3],
                      smaddr(Wt + (warp_n * 64 + pr * 16 + b_row) * WLD2 + ks * 16 + b_col));
                unsigned b01[2] = { b4[0], b4[1] };
                unsigned b23[2] = { b4[2], b4[3] };
                mma_f16(c[0][2 * pr],     a[0], b01);
                mma_f16(c[0][2 * pr + 1], a[0], b23);
                mma_f16(c[1][2 * pr],     a[1], b01);
                mma_f16(c[1][2 * pr + 1], a[1], b23);
            }
        }
    }

    // epilogue: uniform natural layout for Q, K, V
    const int bbatch = m0 / S;
    const int s0     = m0 % S;
    const int bh     = bbatch * H + h;
    __half* Ob = (z == 0 ? g_Q : (z == 1 ? g_K : g_V)) + ((size_t)bh * S + s0) * DH;
    #pragma unroll
    for (int mi = 0; mi < 2; mi++) {
        const int r0 = warp_m * 32 + mi * 16 + g;
        #pragma unroll
        for (int ni = 0; ni < 8; ni++) {
            const int col = warp_n * 64 + ni * 8 + 2 * t4;
            *reinterpret_cast<unsigned*>(Ob + (size_t)r0 * DH + col)
                = pack2(c[mi][ni][0], c[mi][ni][1]);
            *reinterpret_cast<unsigned*>(Ob + (size_t)(r0 + 8) * DH + col)
                = pack2(c[mi][ni][2], c[mi][ni][3]);
        }
    }
}

// ---------------------------------------------------------------------------
// Kernel 2: causal flash attention, FA2 warp layout.
//   CTA = 128 q-rows of one (b,h); 8 warps x 16 full rows. Q frags hoisted.
//   3-stage K/V ring, ONE __syncthreads per KV tile. ex2.approx.f16x2
//   softmax; row-sum l via ones-B mma. V natural [key][d]; PV B-fragments
//   via ldmatrix.x4.trans (272 B row stride -> conflict-free).
// ---------------------------------------------------------------------------
#define QLD 136    // halves; 272 B == 16 mod 128 -> conflict-free ldmatrix
#define KSTG (64*QLD)
#define VSTG (64*QLD)
#define ATTN_SMEM_BYTES ((128*QLD + 3*KSTG + 3*VSTG) * 2)   // 139,264 B

#define SCALE_LOG2E 0.12751744654974748f   // log2(e)/sqrt(128)

__global__ __launch_bounds__(256, 1) void attn_kernel(float* __restrict__ out)
{
    extern __shared__ __half smh[];
    __half* Qs = smh;                    // 128 x QLD
    __half* Ks = Qs + 128*QLD;           // 3 x 64 x QLD
    __half* Vs = Ks + 3*KSTG;            // 3 x 64 x QLD (natural [key][d])

    const int qb = blockIdx.x;
    const int bh = blockIdx.y;
    const int b  = bh >> 4;
    const int h  = bh & 15;
    const int q0 = qb * 128;
    const int tid  = threadIdx.x;
    const int lane = tid & 31;
    const int wid  = tid >> 5;
    const int g  = lane >> 2;
    const int t4 = lane & 3;
    const int rlo = wid * 16 + g;
    const int rhi = rlo + 8;

    const int a_row = wid * 16 + (lane & 7) + ((lane >> 3) & 1) * 8;
    const int a_col = (lane >> 4) * 8;
    const int b_row = (lane & 7) + (lane >> 4) * 8;
    const int b_col = ((lane >> 3) & 1) * 8;
    const int vt_row = lane & 15;          // trans-ldmatrix: key row within 16
    const int vt_col = (lane >> 4) * 8;    // trans-ldmatrix: d col half

    const __half* Kg0 = g_K + (size_t)bh * S * DH;
    const __half* Vg0 = g_V + (size_t)bh * S * DH;

    auto issue_kv = [&](int kb, int st) {
        const __half* Kg = Kg0 + (size_t)kb * 64 * DH;
        const __half* Vg = Vg0 + (size_t)kb * 64 * DH;
        __half* Kd = Ks + st * KSTG;
        __half* Vd = Vs + st * VSTG;
        const int krow = tid >> 2, k1 = tid & 3;
        #pragma unroll
        for (int i = 0; i < 2; i++) {
            const int col = (k1 + 4 * i) * 16;
            cp16(Kd + krow * QLD + col,     Kg + (size_t)krow * DH + col);
            cp16(Kd + krow * QLD + col + 8, Kg + (size_t)krow * DH + col + 8);
            cp16(Vd + krow * QLD + col,     Vg + (size_t)krow * DH + col);
            cp16(Vd + krow * QLD + col + 8, Vg + (size_t)krow * DH + col + 8);
        }
        cp_commit();
    };

    // group 0: Q + K0/V0 ; group 1: K1/V1
    {
        const __half* Qg = g_Q + ((size_t)bh * S + q0) * DH;
        const int qrow = tid >> 1, q1 = tid & 1;
        #pragma unroll
        for (int i = 0; i < 4; i++) {
            const int col = (q1 + 2 * i) * 8;
            cp16(Qs + qrow * QLD + col,      Qg + (size_t)qrow * DH + col);
            cp16(Qs + qrow * QLD + col + 64, Qg + (size_t)qrow * DH + col + 64);
        }
        issue_kv(0, 0);   // commits Q + KV0 together
    }
    issue_kv(1, 1);

    float oacc[16][4];
    #pragma unroll
    for (int i = 0; i < 16; i++)
        #pragma unroll
        for (int j = 0; j < 4; j++) oacc[i][j] = 0.0f;
    float lacc[4] = {0.f, 0.f, 0.f, 0.f};

    unsigned qa[8][4];
    float m0r = -3.0e38f, m1r = -3.0e38f;
    const unsigned ONES2 = 0x3C003C00u;   // half2(1,1)
    const unsigned onesb[2] = { ONES2, ONES2 };

    const int NT = 2 * qb + 2;
    for (int kb = 0; kb < NT; kb++) {
        if (kb + 1 < NT) cp_wait1(); else cp_wait0();
        __syncthreads();
        if (kb + 2 < NT) issue_kv(kb + 2, (kb + 2) % 3);

        if (kb == 0) {   // hoist Q fragments once
            #pragma unroll
            for (int ks = 0; ks < 8; ks++)
                ldsm4(qa[ks][0], qa[ks][1], qa[ks][2], qa[ks][3],
                      smaddr(Qs + a_row * QLD + ks * 16 + a_col));
        }

        const __half* Kb_ = Ks + (kb % 3) * KSTG;
        const __half* Vb_ = Vs + (kb % 3) * VSTG;
        const int k0 = kb * 64;

        // ---- scores ----
        float c[8][4];
        #pragma unroll
        for (int nf = 0; nf < 8; nf++)
            #pragma unroll
            for (int e = 0; e < 4; e++) c[nf][e] = 0.0f;

        #pragma unroll
        for (int ks = 0; ks < 8; ks++) {
            #pragma unroll
            for (int pr = 0; pr < 4; pr++) {
                unsigned b4[4];
                ldsm4(b4[0], b4[1], b4[2], b4[3],
                      smaddr(Kb_ + (pr * 16 + b_row) * QLD + ks * 16 + b_col));
                unsigned b01[2] = { b4[0], b4[1] };
                unsigned b23[2] = { b4[2], b4[3] };
                mma_f16(c[2 * pr],     qa[ks], b01);
                mma_f16(c[2 * pr + 1], qa[ks], b23);
            }
        }

        // scale (log2 domain) + causal mask
        #pragma unroll
        for (int nf = 0; nf < 8; nf++)
            #pragma unroll
            for (int e = 0; e < 4; e++) c[nf][e] *= SCALE_LOG2E;
        if (kb >= 2 * qb) {
            #pragma unroll
            for (int nf = 0; nf < 8; nf++) {
                const int key = k0 + nf * 8 + 2 * t4;
                if (key     > q0 + rlo) c[nf][0] = -1.0e30f;
                if (key + 1 > q0 + rlo) c[nf][1] = -1.0e30f;
                if (key     > q0 + rhi) c[nf][2] = -1.0e30f;
                if (key + 1 > q0 + rhi) c[nf][3] = -1.0e30f;
            }
        }

        // ---- warp-private online softmax (base-2) ----
        float mx0 = -3.0e38f, mx1 = -3.0e38f;
        #pragma unroll
        for (int nf = 0; nf < 8; nf++) {
            mx0 = fmaxf(mx0, fmaxf(c[nf][0], c[nf][1]));
            mx1 = fmaxf(mx1, fmaxf(c[nf][2], c[nf][3]));
        }
        mx0 = fmaxf(mx0, __shfl_xor_sync(0xffffffffu, mx0, 1));
        mx0 = fmaxf(mx0, __shfl_xor_sync(0xffffffffu, mx0, 2));
        mx1 = fmaxf(mx1, __shfl_xor_sync(0xffffffffu, mx1, 1));
        mx1 = fmaxf(mx1, __shfl_xor_sync(0xffffffffu, mx1, 2));
        const float mn0 = fmaxf(m0r, mx0);
        const float mn1 = fmaxf(m1r, mx1);
        const float cr0 = exp2f(m0r - mn0);
        const float cr1 = exp2f(m1r - mn1);
        m0r = mn0;
        m1r = mn1;

        // probabilities straight to fp16 a-fragments (2^x, packed)
        unsigned pa[4][4];
        #pragma unroll
        for (int ks = 0; ks < 4; ks++) {
            pa[ks][0] = exp2h2(c[2 * ks][0] - mn0,     c[2 * ks][1] - mn0);
            pa[ks][1] = exp2h2(c[2 * ks][2] - mn1,     c[2 * ks][3] - mn1);
            pa[ks][2] = exp2h2(c[2 * ks + 1][0] - mn0, c[2 * ks + 1][1] - mn0);
            pa[ks][3] = exp2h2(c[2 * ks + 1][2] - mn1, c[2 * ks + 1][3] - mn1);
        }

        // rescale O and l accumulators
        #pragma unroll
        for (int nf = 0; nf < 16; nf++) {
            oacc[nf][0] *= cr0; oacc[nf][1] *= cr0;
            oacc[nf][2] *= cr1; oacc[nf][3] *= cr1;
        }
        lacc[0] *= cr0; lacc[1] *= cr0; lacc[2] *= cr1; lacc[3] *= cr1;

        // ---- PV + row-sum mma (V natural, B-frags via ldmatrix.trans) ----
        #pragma unroll
        for (int ks = 0; ks < 4; ks++) {
            #pragma unroll
            for (int pr = 0; pr < 8; pr++) {
                unsigned b4[4];
                ldsm4t(b4[0], b4[1], b4[2], b4[3],
                       smaddr(Vb_ + (ks * 16 + vt_row) * QLD + pr * 16 + vt_col));
                unsigned b01[2] = { b4[0], b4[1] };
                unsigned b23[2] = { b4[2], b4[3] };
                mma_f16(oacc[2 * pr],     pa[ks], b01);
                mma_f16(oacc[2 * pr + 1], pa[ks], b23);
            }
            mma_f16(lacc, pa[ks], onesb);   // l += P . 1
        }
    }

    // epilogue: normalize, round(x,4), write [B,S,H*DH]
    const float li0 = 1.0f / lacc[0];
    const float li1 = 1.0f / lacc[2];
    float* og0 = out + ((size_t)(b * S + q0 + rlo)) * (H * DH) + h * DH;
    float* og1 = out + ((size_t)(b * S + q0 + rhi)) * (H * DH) + h * DH;
    #pragma unroll
    for (int nf = 0; nf < 16; nf++) {
        const int col = nf * 8 + 2 * t4;
        float2 v0, v1;
        v0.x = rintf(oacc[nf][0] * li0 * 1.0e4f) * 1.0e-4f;
        v0.y = rintf(oacc[nf][1] * li0 * 1.0e4f) * 1.0e-4f;
        v1.x = rintf(oacc[nf][2] * li1 * 1.0e4f) * 1.0e-4f;
        v1.y = rintf(oacc[nf][3] * li1 * 1.0e4f) * 1.0e-4f;
        *reinterpret_cast<float2*>(og0 + col) = v0;
        *reinterpret_cast<float2*>(og1 + col) = v1;
    }
}

// ---------------------------------------------------------------------------
extern "C" void kernel_launch(void* const* d_in, const int* in_sizes, int n_in,
                              void* d_out, int out_size)
{
    const float* X  = (const float*)d_in[0];
    const float* Wq = (const float*)d_in[1];
    const float* Wk = (const float*)d_in[2];
    const float* Wv = (const float*)d_in[3];
    float* out = (float*)d_out;

    cudaFuncSetAttribute(qkv_kernel,  cudaFuncAttributeMaxDynamicSharedMemorySize, QKV_SMEM_BYTES);
    cudaFuncSetAttribute(attn_kernel, cudaFuncAttributeMaxDynamicSharedMemorySize, ATTN_SMEM_BYTES);

    static __half *pXh = nullptr, *pWq = nullptr, *pWk = nullptr, *pWv = nullptr;
    if (!pXh) {
        cudaGetSymbolAddress((void**)&pXh, g_Xh);
        cudaGetSymbolAddress((void**)&pWq, g_Wtq);
        cudaGetSymbolAddress((void**)&pWk, g_Wtk);
        cudaGetSymbolAddress((void**)&pWv, g_Wtv);
    }

    convX<<<2048, 256>>>(X, pXh, (int)((size_t)BS * E / 4));
    dim3 gt(DH / 32, E / 32, 3 * H);
    convWT<<<gt, dim3(32, 8)>>>(Wq, Wk, Wv, pWq, pWk, pWv);

    dim3 g1(H, BS / 128, 3);
    qkv_kernel<<<g1, 256, QKV_SMEM_BYTES>>>();

    dim3 g2(S / 128, B * H);
    attn_kernel<<<g2, 256, ATTN_SMEM_BYTES>>>(out);
}